// round 3
// baseline (speedup 1.0000x reference)
#include <cuda_runtime.h>
#include <cuda_bf16.h>

// DConv: per-channel cyclic shift (on 1-padded 162x162 grid) followed by 3x3
// conv (pad 1) and center crop. Crop cancels conv padding, so:
//   out[b,co,oy,ox] = sum_{ci,ky,kx} w[co,ci,ky,kx] * xs[b,ci,oy+ky,ox+kx]
// with xs(i,j) = x[p-1,q-1] if p,q in [1,160] else 0,
//   p = (i - dy[ci%5]) mod 162, q = (j - dx[ci%5]) mod 162,
//   dy = {0,0,1,0,-1}, dx = {0,1,0,-1,0}.

#define TILE_H 32
#define TILE_W 32
#define CO_PER 8
#define SM_STRIDE 35   // (TILE_W+2)=34 padded to 35: conflict-free access pattern

__global__ __launch_bounds__(256, 2)
void dconv_kernel(const float* __restrict__ x,
                  const float* __restrict__ w,
                  float* __restrict__ out) {
    __shared__ float xs[(TILE_H + 2) * SM_STRIDE];
    __shared__ float ws[CO_PER * 9];

    const int tid = threadIdx.x;
    const int ox0 = blockIdx.x * TILE_W;
    const int oy0 = blockIdx.y * TILE_H;
    const int bz  = blockIdx.z;           // b * 8 + co_group
    const int b   = bz >> 3;
    const int co0 = (bz & 7) * CO_PER;

    const int tw = tid & 7;    // 0..7  -> 4 cols each
    const int th = tid >> 3;   // 0..31 -> row

    float acc[CO_PER][4];
#pragma unroll
    for (int c = 0; c < CO_PER; ++c)
#pragma unroll
        for (int p = 0; p < 4; ++p) acc[c][p] = 0.0f;

    const float* xb = x + (size_t)b * 64 * 160 * 160;

    for (int ci = 0; ci < 64; ++ci) {
        const int cm = ci % 5;
        const int dy = (cm == 2) ? 1 : ((cm == 4) ? -1 : 0);
        const int dx = (cm == 1) ? 1 : ((cm == 3) ? -1 : 0);
        const float* xc = xb + (size_t)ci * 160 * 160;

        // Stage shifted tile (TILE_H+2) x (TILE_W+2) into smem.
#pragma unroll
        for (int e = tid; e < (TILE_H + 2) * (TILE_W + 2); e += 256) {
            const int ti = e / (TILE_W + 2);
            const int tj = e % (TILE_W + 2);
            int p = oy0 + ti - dy;             // in [-1, 162]
            int q = ox0 + tj - dx;
            if (p < 0) p += 162; else if (p >= 162) p -= 162;
            if (q < 0) q += 162; else if (q >= 162) q -= 162;
            float v = 0.0f;
            if (p >= 1 && p <= 160 && q >= 1 && q <= 160)
                v = xc[(p - 1) * 160 + (q - 1)];
            xs[ti * SM_STRIDE + tj] = v;
        }
        // Stage weights for this ci: w[co0..co0+7][ci][0..8]
        if (tid < CO_PER * 9) {
            const int c = tid / 9, k = tid % 9;
            ws[tid] = w[((size_t)(co0 + c) * 64 + ci) * 9 + k];
        }
        __syncthreads();

        // Each thread: 3 rows x 6 cols of xs -> 4 output pixels.
        float xv[3][6];
#pragma unroll
        for (int r = 0; r < 3; ++r)
#pragma unroll
            for (int c2 = 0; c2 < 6; ++c2)
                xv[r][c2] = xs[(th + r) * SM_STRIDE + tw * 4 + c2];

#pragma unroll
        for (int c = 0; c < CO_PER; ++c) {
            float wr[9];
#pragma unroll
            for (int k = 0; k < 9; ++k) wr[k] = ws[c * 9 + k];
#pragma unroll
            for (int p = 0; p < 4; ++p)
#pragma unroll
                for (int ky = 0; ky < 3; ++ky)
#pragma unroll
                    for (int kx = 0; kx < 3; ++kx)
                        acc[c][p] = fmaf(wr[ky * 3 + kx], xv[ky][p + kx], acc[c][p]);
        }
        __syncthreads();
    }

    const int oy = oy0 + th;
    const int oxb = ox0 + tw * 4;
#pragma unroll
    for (int c = 0; c < CO_PER; ++c) {
        float4 v = make_float4(acc[c][0], acc[c][1], acc[c][2], acc[c][3]);
        *reinterpret_cast<float4*>(
            &out[(((size_t)b * 64 + co0 + c) * 160 + oy) * 160 + oxb]) = v;
    }
}

extern "C" void kernel_launch(void* const* d_in, const int* in_sizes, int n_in,
                              void* d_out, int out_size) {
    const float* x = (const float*)d_in[0];
    const float* w = (const float*)d_in[1];
    float* out = (float*)d_out;
    (void)in_sizes; (void)n_in; (void)out_size;

    dim3 grid(160 / TILE_W, 160 / TILE_H, 16 * (64 / CO_PER));  // 5 x 5 x 128
    dim3 block(256);
    dconv_kernel<<<grid, block>>>(x, w, out);
}

// round 6
// speedup vs baseline: 6.3037x; 6.3037x over previous
#include <cuda_runtime.h>
#include <cstdint>

// DConv as implicit GEMM on classic mma.sync (tf32, m16n8k8) — tcgen05 is
// rejected by this harness's compute_103 ptxas target.
// out[b,co,oy,ox] = sum_{ci,ky,kx} w[co,ci,ky,kx] * xs[b,ci,oy+ky,ox+kx]
// xs = shift+zero-padded 162x162 grid (crop cancels conv padding).
// CTA tile: 256 pixels (16y x 16x), N=64 co, K=576 = 18 chunks of 32
// (chunk c: tap s=c>>1 -> ky,kx; half h=c&1 of ci).
// A: 18x18 pixel neighborhood, channels-last, resident in smem per tile.
// B: all 18 chunks resident in smem for the whole kernel.

__device__ __align__(256) float g_xpt[(size_t)16 * 162 * 162 * 64];
__device__ __align__(256) float g_wperm[18 * 2048];

__device__ __forceinline__ uint32_t smem_u32(const void* p) {
    uint32_t a;
    asm("{ .reg .u64 t; cvta.to.shared.u64 t, %1; cvt.u32.u64 %0, t; }" : "=r"(a) : "l"(p));
    return a;
}
__device__ __forceinline__ float tf32r(float v) {
    uint32_t b;
    asm("cvt.rna.tf32.f32 %0, %1;" : "=r"(b) : "f"(v));
    return __uint_as_float(b);
}
__device__ __forceinline__ void lds64(uint32_t& x, uint32_t& y, uint32_t addr) {
    asm volatile("ld.shared.v2.b32 {%0,%1}, [%2];" : "=r"(x), "=r"(y) : "r"(addr));
}
__device__ __forceinline__ void mma_tf32(float* d, const uint32_t* a,
                                         uint32_t b0, uint32_t b1) {
    asm volatile(
        "mma.sync.aligned.m16n8k8.row.col.f32.tf32.tf32.f32 "
        "{%0,%1,%2,%3}, {%4,%5,%6,%7}, {%8,%9}, {%0,%1,%2,%3};"
        : "+f"(d[0]), "+f"(d[1]), "+f"(d[2]), "+f"(d[3])
        : "r"(a[0]), "r"(a[1]), "r"(a[2]), "r"(a[3]), "r"(b0), "r"(b1));
}
#define CP_ASYNC16(dst, src) \
    asm volatile("cp.async.cg.shared.global [%0], [%1], 16;" :: "r"(dst), "l"(src))
#define CP_COMMIT() asm volatile("cp.async.commit_group;" ::: "memory")
#define CP_WAIT0()  asm volatile("cp.async.wait_group 0;" ::: "memory")

// ci position within the 64-float channels-last pixel vector:
// half h = ci>=32; within half: kstep t = kk>>3, col c = kk&7 stored at
// t*8 + 2*(c&3) + (c>>2)  -> makes (c, c+4) adjacent for LDS.64 frag loads.
__device__ __forceinline__ int pos64(int ci) {
    int kk = ci & 31, t = kk >> 3, cc = kk & 7;
    return (ci & 32) + t * 8 + 2 * (cc & 3) + (cc >> 2);
}

// ---------------- prep: xpt[b][i][j][pos64(ci)] channels-last, tf32 ----------------
__global__ __launch_bounds__(256) void prep_x(const float* __restrict__ x) {
    __shared__ float tile[32][65];
    const int jc = blockIdx.x, i = blockIdx.y, b = blockIdx.z;
    const int j0 = jc * 32;
    const int w = (162 - j0 < 32) ? (162 - j0) : 32;
    const int tid = threadIdx.x;
    const int n = 64 * w;
    const float* xb = x + (size_t)b * 64 * 25600;

    for (int e = tid; e < n; e += 256) {
        int ci = e / w, jj = e - ci * w;
        int cm = ci % 5;
        int dy = (cm == 2) ? 1 : ((cm == 4) ? -1 : 0);
        int dx = (cm == 1) ? 1 : ((cm == 3) ? -1 : 0);
        int p = i - dy;       if (p < 0) p += 162; else if (p >= 162) p -= 162;
        int q = j0 + jj - dx; if (q < 0) q += 162; else if (q >= 162) q -= 162;
        float v = 0.0f;
        if (p >= 1 && p <= 160 && q >= 1 && q <= 160)
            v = tf32r(xb[(size_t)ci * 25600 + (p - 1) * 160 + (q - 1)]);
        tile[jj][pos64(ci)] = v;
    }
    __syncthreads();
    size_t base = (((size_t)b * 162 + i) * 162 + j0) * 64;
    for (int e = tid; e < n; e += 256) {
        int jj = e >> 6, ci = e & 63;
        g_xpt[base + (size_t)jj * 64 + ci] = tile[jj][ci];
    }
}

// B image per chunk: 64 rows (co) x 128B (32 permuted tf32), 16B-slot swizzled by co&7.
__global__ void prep_w(const float* __restrict__ w) {
    int id = blockIdx.x * 256 + threadIdx.x;
    if (id >= 18 * 2048) return;
    int c = id >> 11, rr = id & 2047, co = rr >> 5, kk = rr & 31;
    int t = kk >> 3, cc = kk & 7;
    uint32_t off = (uint32_t)co * 128u + (uint32_t)(t * 8 + 2 * (cc & 3) + (cc >> 2)) * 4u;
    uint32_t swz = off ^ ((off >> 3) & 0x70u);
    int ci = (c & 1) * 32 + kk, s = c >> 1;
    g_wperm[c * 2048 + (swz >> 2)] = tf32r(w[((size_t)co * 64 + ci) * 9 + s]);
}

// ---------------- main MMA kernel ----------------
#define A_BYTES 82944            // 18*18 pixels * 256B
#define SMEM_BYTES (A_BYTES + 18 * 8192)   // 230400

__global__ __launch_bounds__(256, 1) void dconv_mma(float* __restrict__ out) {
    extern __shared__ char smem[];
    const uint32_t sb = smem_u32(smem);
    const uint32_t a_sb = sb;
    const uint32_t b_sb = sb + A_BYTES;
    const int tid = threadIdx.x;
    const int w = tid >> 5, l = tid & 31, q = l >> 2, r = l & 3;

    // Stage all B chunks once (already permuted + swizzled).
    for (int idx = tid; idx < 9216; idx += 256)
        CP_ASYNC16(b_sb + (uint32_t)idx * 16u, (const char*)g_wperm + (size_t)idx * 16);
    CP_COMMIT();
    CP_WAIT0();
    __syncthreads();

    for (int tile = blockIdx.x; tile < 1600; tile += gridDim.x) {
        const int b  = tile / 100, rr = tile % 100;
        const int y0 = (rr / 10) * 16, x0 = (rr % 10) * 16;
        const float* xt = g_xpt + (size_t)b * 26244 * 64;

        __syncthreads();   // previous tile's A fully consumed by all warps
        // Stage 18x18 neighborhood: pixel p at p*256, 16B slot s at (s ^ (x&7))<<4.
        for (int e = tid; e < 5184; e += 256) {
            int p = e >> 4, s = e & 15;
            int row = p / 18, col = p - row * 18;
            const float* src = xt + ((size_t)(y0 + row) * 162 + (x0 + col)) * 64 + s * 4;
            CP_ASYNC16(a_sb + (uint32_t)p * 256u + (uint32_t)((s ^ (col & 7)) << 4), src);
        }
        CP_COMMIT();
        CP_WAIT0();
        __syncthreads();

        float acc[2][8][4];
#pragma unroll
        for (int i = 0; i < 2; ++i)
#pragma unroll
            for (int j = 0; j < 8; ++j)
#pragma unroll
                for (int k = 0; k < 4; ++k) acc[i][j][k] = 0.0f;

#pragma unroll 1
        for (int c = 0; c < 18; ++c) {
            const int s9 = c >> 1, h = c & 1;
            const int ky = (s9 >= 6) ? 2 : (s9 >= 3 ? 1 : 0);
            const int kx = s9 - ky * 3;
            const uint32_t bb = b_sb + (uint32_t)c * 8192u;
            const int xn0 = q + kx, xn1 = q + 8 + kx;
            const uint32_t rowb = (uint32_t)((2 * w + ky) * 18);
            const uint32_t p0 = a_sb + (rowb + (uint32_t)xn0) * 256u;
            const uint32_t p1 = a_sb + (rowb + (uint32_t)xn1) * 256u;
            const uint32_t k0 = (uint32_t)(xn0 & 7) << 4;
            const uint32_t k1 = (uint32_t)(xn1 & 7) << 4;
            const uint32_t bq = (uint32_t)q << 4;
            const uint32_t ob = (uint32_t)(h * 128 + 8 * r);
#pragma unroll
            for (int t = 0; t < 4; ++t) {
                const uint32_t off = ob + (uint32_t)(t * 32);
                uint32_t A0[4], A1[4];
                lds64(A0[0], A0[2], p0 + (off ^ k0));
                lds64(A0[1], A0[3], p1 + (off ^ k1));
                lds64(A1[0], A1[2], p0 + 4608u + (off ^ k0));   // yn+1 = +18*256
                lds64(A1[1], A1[3], p1 + 4608u + (off ^ k1));
#pragma unroll
                for (int nf = 0; nf < 8; ++nf) {
                    uint32_t b0, b1;
                    uint32_t boff = (uint32_t)((nf * 8 + q) * 128 + t * 32 + 8 * r);
                    lds64(b0, b1, bb + (boff ^ bq));
                    mma_tf32(acc[0][nf], A0, b0, b1);
                    mma_tf32(acc[1][nf], A1, b0, b1);
                }
            }
        }

        // Epilogue: frag (mf,nf): rows y0+2w+mf, x = x0+q / x0+q+8, co = nf*8+2r (+1).
#pragma unroll
        for (int mf = 0; mf < 2; ++mf) {
            const int y = y0 + 2 * w + mf;
#pragma unroll
            for (int nf = 0; nf < 8; ++nf) {
                const int co = nf * 8 + 2 * r;
                float* op = out + (((size_t)b * 64 + co) * 160 + y) * 160 + x0;
                op[q]             = acc[mf][nf][0];
                op[25600 + q]     = acc[mf][nf][1];
                op[q + 8]         = acc[mf][nf][2];
                op[25600 + q + 8] = acc[mf][nf][3];
            }
        }
    }
}

extern "C" void kernel_launch(void* const* d_in, const int* in_sizes, int n_in,
                              void* d_out, int out_size) {
    const float* x = (const float*)d_in[0];
    const float* w = (const float*)d_in[1];
    float* out = (float*)d_out;
    (void)in_sizes; (void)n_in; (void)out_size;

    prep_x<<<dim3(6, 162, 16), 256>>>(x);
    prep_w<<<144, 256>>>(w);
    cudaFuncSetAttribute(dconv_mma, cudaFuncAttributeMaxDynamicSharedMemorySize, SMEM_BYTES);
    dconv_mma<<<148, 256, SMEM_BYTES>>>(out);
}